// round 5
// baseline (speedup 1.0000x reference)
#include <cuda_runtime.h>
#include <math.h>
#include <stdint.h>

// ---------------- problem constants ----------------
#define BB   4
#define SS   512
#define HH   512
#define NHH  8
#define TT   3
#define DHH  64
#define DTS  170
#define BS   (BB*SS)             // 2048
#define BSS  (BB*SS*SS)          // 1,048,576
#define EPS  1e-5f

// mask lookup table
#define NTAB   4096
#define M0MAX  5.6400f
#define TABENT (NTAB+1)
#define TABSZ  (3*2*TABENT + 3)

// ---------------- scratch layout (floats) ----------------
#define OFF_MASK     ((size_t)0)                         // 3 * BSS
#define OFF_QKV      (OFF_MASK + (size_t)3*BSS)          // 3 * BS * 1536
#define OFF_ATTNO    (OFF_QKV + (size_t)3*BS*1536)       // 3 * BS * HH
#define OFF_COMB     (OFF_ATTNO + (size_t)3*BS*HH)       // BS*1536
#define OFF_MACT     (OFF_COMB + (size_t)BS*1536)
#define OFF_WEIGHTED (OFF_MACT + (size_t)BS*HH)
#define OFF_SA       (OFF_WEIGHTED + (size_t)BS*HH)
#define OFF_H1       (OFF_SA + (size_t)BS*HH)
#define OFF_FF       (OFF_H1 + (size_t)BS*HH)            // BS*2048
#define OFF_FFO      (OFF_FF + (size_t)BS*2048)
#define OFF_H2       (OFF_FFO + (size_t)BS*HH)
#define OFF_OP       (OFF_H2 + (size_t)BS*HH)
#define OFF_TAB      (OFF_OP + (size_t)BS*HH)
#define SCRATCH_FLOATS (OFF_TAB + (size_t)TABSZ)

__device__ float g_scratch[SCRATCH_FLOATS];

// ---------------- helpers ----------------
__device__ __forceinline__ float gelu_exact(float x) {
    return 0.5f * x * (1.0f + erff(x * 0.70710678118654752f));
}
__device__ __forceinline__ float warp_sum(float x) {
    #pragma unroll
    for (int o = 16; o > 0; o >>= 1) x += __shfl_xor_sync(0xffffffffu, x, o);
    return x;
}
__device__ __forceinline__ float to_tf32(float x) {
    uint32_t u;
    asm("cvt.rna.tf32.f32 %0, %1;" : "=r"(u) : "f"(x));
    return __uint_as_float(u);
}
__device__ __forceinline__ void mma_tf32(float* c, const float* a, const float* b) {
    asm volatile(
        "mma.sync.aligned.m16n8k8.row.col.f32.tf32.tf32.f32 "
        "{%0,%1,%2,%3}, {%4,%5,%6,%7}, {%8,%9}, {%0,%1,%2,%3};\n"
        : "+f"(c[0]), "+f"(c[1]), "+f"(c[2]), "+f"(c[3])
        : "r"(__float_as_uint(a[0])), "r"(__float_as_uint(a[1])),
          "r"(__float_as_uint(a[2])), "r"(__float_as_uint(a[3])),
          "r"(__float_as_uint(b[0])), "r"(__float_as_uint(b[1])));
}
// k-permutation inside a group of 8 (used only by flash P/V staging)
__device__ __forceinline__ int perm8(int k) {
    return (k & ~7) + ((k & 3) << 1) + ((k >> 2) & 1);
}

// ---------------- mask table build ----------------
__global__ void tab_kernel(const float* __restrict__ enc_W,
                           const float* __restrict__ enc_b,
                           const float* __restrict__ enc_g,
                           const float* __restrict__ enc_be,
                           float* __restrict__ tab)
{
    int w = (blockIdx.x * blockDim.x + threadIdx.x) >> 5;
    int lane = threadIdx.x & 31;
    const int NE = 3 * 2 * TABENT;
    if (w >= NE + 3) return;
    int i; float dir, mag;
    if (w < NE) {
        i = w / (2 * TABENT);
        int r = w - i * (2 * TABENT);
        int d = r / TABENT;
        int j = r - d * TABENT;
        dir = d ? 1.f : -1.f;
        float m0 = (float)j * (M0MAX / NTAB);
        float sc = (i == 0) ? 1.f : ((i == 1) ? 0.1f : 0.01f);
        mag = m0 * sc;
    } else {
        i = w - NE; dir = 0.f; mag = 0.f;
    }
    const float* W0 = enc_W + (size_t)(i*2+0)*DTS;
    const float* W1 = enc_W + (size_t)(i*2+1)*DTS;
    const float* bb = enc_b + (size_t)i*DTS;
    const float* gg = enc_g + (size_t)i*DTS;
    const float* be = enc_be + (size_t)i*DTS;

    float e[6];
    float s = 0.f, ss = 0.f;
    #pragma unroll
    for (int j2 = 0; j2 < 6; j2++) {
        int d = lane + 32*j2;
        float v = 0.f;
        if (d < DTS) v = dir*W0[d] + mag*W1[d] + bb[d];
        e[j2] = v; s += v; ss += v*v;
    }
    s  = warp_sum(s);
    ss = warp_sum(ss);
    float mean = s * (1.f/DTS);
    float var  = ss * (1.f/DTS) - mean*mean;
    float rs = rsqrtf(var + EPS);
    float gs = 0.f;
    #pragma unroll
    for (int j2 = 0; j2 < 6; j2++) {
        int d = lane + 32*j2;
        if (d < DTS) {
            float y = (e[j2] - mean) * rs * gg[d] + be[d];
            gs += gelu_exact(y);
        }
    }
    gs = warp_sum(gs);
    if (lane == 0) tab[w] = gs * (1.f/DTS);
}

// ---------------- mask fill via table interpolation ----------------
__global__ void maskfill_kernel(const float* __restrict__ ts,
                                const float* __restrict__ tab,
                                float* __restrict__ masks)
{
    int idx = blockIdx.x * blockDim.x + threadIdx.x;
    if (idx >= BSS) return;
    int b = idx >> 18;
    int q = (idx >> 9) & 511;
    int k = idx & 511;
    float dt = ts[(b << 9) + q] - ts[(b << 9) + k];
    if (dt == 0.f) {
        #pragma unroll
        for (int i = 0; i < TT; i++)
            masks[(size_t)i*BSS + idx] = tab[3*2*TABENT + i];
    } else {
        int d = dt > 0.f ? 1 : 0;
        float m0 = log1pf(fabsf(dt) * (1.f/3600.f));
        float t = m0 * ((float)NTAB / M0MAX);
        t = fminf(t, (float)NTAB - 1e-3f);
        int j = (int)t;
        float f = t - (float)j;
        #pragma unroll
        for (int i = 0; i < TT; i++) {
            const float* tb = tab + (size_t)(i*2 + d) * TABENT;
            float a = tb[j];
            masks[(size_t)i*BSS + idx] = a + f * (tb[j+1] - a);
        }
    }
}

// ---------------- tf32 tensor-core GEMM v2: BM=BN=128, BK=32, double-buffered ----------------
// dynamic smem 71680B. grid (N/128, M/128, z). 256 threads (8 warps 2x4).
#define G2_SA_STRIDE 36
#define G2_SB_STRIDE 136
#define G2_SA_BUF (128*G2_SA_STRIDE)        // 4608 floats
#define G2_SB_BUF (32*G2_SB_STRIDE)         // 4352 floats
#define G2_SMEM_BYTES ((2*G2_SA_BUF + 2*G2_SB_BUF)*4)

template<int GELU>
__global__ __launch_bounds__(256, 2)
void gemm_tc2(const float* __restrict__ A0, int lda,
              const float* __restrict__ B0, int ldb,
              const float* __restrict__ bias0,
              float* __restrict__ C0, int ldc, int K,
              size_t sAz, size_t sBz, size_t sCz, size_t sbz)
{
    extern __shared__ float smem[];
    float* sA = smem;                        // [2][128][36]
    float* sB = smem + 2*G2_SA_BUF;          // [2][32][136]

    const int tid  = threadIdx.x;
    const int lane = tid & 31;
    const int warp = tid >> 5;
    const int wm = warp & 1;
    const int wn = warp >> 1;
    const int g = lane >> 2;
    const int c = lane & 3;

    const int bm = blockIdx.y * 128;
    const int bn = blockIdx.x * 128;
    const int z  = blockIdx.z;

    const float* A = A0 + (size_t)z * sAz;
    const float* B = B0 + (size_t)z * sBz;
    const float* bias = bias0 + (size_t)z * sbz;
    float* C = C0 + (size_t)z * sCz;

    // A staging: thread -> row ar (0..127), k half ah (0 or 16); 4 float4
    const int ar = tid >> 1;
    const int ah = (tid & 1) * 16;
    const float* aP = A + (size_t)(bm + ar)*lda + ah;
    float* sArow = sA + ar*G2_SA_STRIDE + ah;

    // B staging: thread -> rows bkr+8p (p=0..3), 4 cols at bnc; coalesced
    const int bkr = tid >> 5;
    const int bnc = (tid & 31) * 4;
    const float* bP = B + (size_t)bkr*ldb + bn + bnc;
    float* sBbase = sB + bkr*G2_SB_STRIDE + bnc;

    float acc[4][4][4];
    #pragma unroll
    for (int i = 0; i < 4; i++)
        #pragma unroll
        for (int j = 0; j < 4; j++)
            #pragma unroll
            for (int q = 0; q < 4; q++) acc[i][j][q] = 0.f;

    auto stA = [&](int buf, int off, float4 v) {
        float* p = sArow + buf*G2_SA_BUF + off;
        p[0] = to_tf32(v.x); p[1] = to_tf32(v.y);
        p[2] = to_tf32(v.z); p[3] = to_tf32(v.w);
    };
    auto stB = [&](int buf, int p, float4 v) {
        float* q = sBbase + buf*G2_SB_BUF + p*8*G2_SB_STRIDE;
        q[0] = to_tf32(v.x); q[1] = to_tf32(v.y);
        q[2] = to_tf32(v.z); q[3] = to_tf32(v.w);
    };

    const int nstage = K / 32;

    // prologue: stage 0
    {
        float4 a0 = *(const float4*)(aP);
        float4 a1 = *(const float4*)(aP + 4);
        float4 a2 = *(const float4*)(aP + 8);
        float4 a3 = *(const float4*)(aP + 12);
        float4 b0 = *(const float4*)(bP);
        float4 b1 = *(const float4*)(bP + (size_t)8*ldb);
        float4 b2 = *(const float4*)(bP + (size_t)16*ldb);
        float4 b3 = *(const float4*)(bP + (size_t)24*ldb);
        stA(0, 0, a0); stA(0, 4, a1); stA(0, 8, a2); stA(0, 12, a3);
        stB(0, 0, b0); stB(0, 1, b1); stB(0, 2, b2); stB(0, 3, b3);
    }
    __syncthreads();

    for (int s = 0; s < nstage; s++) {
        const int cur = s & 1;
        const int nxt = cur ^ 1;
        const bool more = (s + 1 < nstage);
        const float* sAc = sA + cur*G2_SA_BUF;
        const float* sBc = sB + cur*G2_SB_BUF;

        float4 a0, a1, b0, b1;
        if (more) {
            const int k1 = (s + 1) * 32;
            a0 = *(const float4*)(aP + k1);
            a1 = *(const float4*)(aP + k1 + 4);
            b0 = *(const float4*)(bP + (size_t)k1*ldb);
            b1 = *(const float4*)(bP + (size_t)(k1 + 8)*ldb);
        }

        // kk = 0,1
        #pragma unroll
        for (int kk = 0; kk < 2; kk++) {
            const int kb = kk * 8;
            float af[4][4];
            #pragma unroll
            for (int mt = 0; mt < 4; mt++) {
                const float* ap = sAc + (wm*64 + mt*16 + g)*G2_SA_STRIDE + kb;
                af[mt][0] = ap[c];
                af[mt][1] = ap[8*G2_SA_STRIDE + c];
                af[mt][2] = ap[c + 4];
                af[mt][3] = ap[8*G2_SA_STRIDE + c + 4];
            }
            float bf[4][2];
            #pragma unroll
            for (int nt = 0; nt < 4; nt++) {
                const int n0 = wn*32 + nt*8 + g;
                bf[nt][0] = sBc[(kb + c)*G2_SB_STRIDE + n0];
                bf[nt][1] = sBc[(kb + c + 4)*G2_SB_STRIDE + n0];
            }
            #pragma unroll
            for (int mt = 0; mt < 4; mt++)
                #pragma unroll
                for (int nt = 0; nt < 4; nt++)
                    mma_tf32(acc[mt][nt], af[mt], bf[nt]);
        }

        float4 a2, a3, b2, b3;
        if (more) {
            stA(nxt, 0, a0); stA(nxt, 4, a1);
            stB(nxt, 0, b0); stB(nxt, 1, b1);
            const int k1 = (s + 1) * 32;
            a2 = *(const float4*)(aP + k1 + 8);
            a3 = *(const float4*)(aP + k1 + 12);
            b2 = *(const float4*)(bP + (size_t)(k1 + 16)*ldb);
            b3 = *(const float4*)(bP + (size_t)(k1 + 24)*ldb);
        }

        // kk = 2,3
        #pragma unroll
        for (int kk = 2; kk < 4; kk++) {
            const int kb = kk * 8;
            float af[4][4];
            #pragma unroll
            for (int mt = 0; mt < 4; mt++) {
                const float* ap = sAc + (wm*64 + mt*16 + g)*G2_SA_STRIDE + kb;
                af[mt][0] = ap[c];
                af[mt][1] = ap[8*G2_SA_STRIDE + c];
                af[mt][2] = ap[c + 4];
                af[mt][3] = ap[8*G2_SA_STRIDE + c + 4];
            }
            float bf[4][2];
            #pragma unroll
            for (int nt = 0; nt < 4; nt++) {
                const int n0 = wn*32 + nt*8 + g;
                bf[nt][0] = sBc[(kb + c)*G2_SB_STRIDE + n0];
                bf[nt][1] = sBc[(kb + c + 4)*G2_SB_STRIDE + n0];
            }
            #pragma unroll
            for (int mt = 0; mt < 4; mt++)
                #pragma unroll
                for (int nt = 0; nt < 4; nt++)
                    mma_tf32(acc[mt][nt], af[mt], bf[nt]);
        }

        if (more) {
            stA(nxt, 8, a2); stA(nxt, 12, a3);
            stB(nxt, 2, b2); stB(nxt, 3, b3);
        }
        __syncthreads();
    }

    // epilogue
    #pragma unroll
    for (int mt = 0; mt < 4; mt++) {
        const int row = bm + wm*64 + mt*16 + g;
        #pragma unroll
        for (int nt = 0; nt < 4; nt++) {
            const int col = bn + wn*32 + nt*8 + c*2;
            float2 bb = *(const float2*)(bias + col);
            float v00 = acc[mt][nt][0] + bb.x, v01 = acc[mt][nt][1] + bb.y;
            float v10 = acc[mt][nt][2] + bb.x, v11 = acc[mt][nt][3] + bb.y;
            if (GELU) {
                v00 = gelu_exact(v00); v01 = gelu_exact(v01);
                v10 = gelu_exact(v10); v11 = gelu_exact(v11);
            }
            *(float2*)(C + (size_t)row*ldc + col) = make_float2(v00, v01);
            *(float2*)(C + (size_t)(row+8)*ldc + col) = make_float2(v10, v11);
        }
    }
}

// ---------------- fused flash attention (tf32) ----------------
// grid (S/64, B*NH, T). Block 128 thr (4 warps), q-tile 64, kv-tile 64.
#define QT 64
#define KT 64
#define FSTR 72

__global__ __launch_bounds__(128, 3)
void flash_kernel(const float* __restrict__ qkvb,
                  const float* __restrict__ maskb,
                  float* __restrict__ attnob)
{
    __shared__ float sKP[QT][FSTR];   // Q, then per-tile K, then per-tile P
    __shared__ float sV[DHH][FSTR];   // V transposed: [dh][perm(kv)]

    const int qt = blockIdx.x;
    const int bh = blockIdx.y;
    const int t  = blockIdx.z;
    const int b = bh >> 3, h = bh & 7;
    const int tid = threadIdx.x;
    const int lane = tid & 31, warp = tid >> 5;
    const int g = lane >> 2, c = lane & 3;
    const int r0 = warp*16 + g, r1 = r0 + 8;

    const float* Qp = qkvb + (size_t)t*BS*1536 + (size_t)b*SS*1536 + h*DHH;
    const float* Kp = Qp + HH;
    const float* Vp = Qp + 2*HH;
    const float* Mp = maskb ? (maskb + (size_t)t*BSS + (size_t)b*SS*SS + (size_t)(qt*QT)*SS)
                            : nullptr;
    float* Op = attnob + (size_t)t*BS*HH + (size_t)b*SS*HH + h*DHH + (size_t)(qt*QT)*HH;

    const int srow = tid >> 1;
    const int shalf = tid & 1;
    const int sprow = perm8(srow & 7) + (srow & ~7);

    // ---- stage Q ----
    {
        const float* src = Qp + (size_t)(qt*QT + srow)*1536 + shalf*32;
        #pragma unroll
        for (int j = 0; j < 8; j++) {
            float4 v = *(const float4*)(src + j*4);
            int k0 = shalf*32 + j*4;
            int grp = k0 & ~7, base = (k0 >> 2) & 1;
            sKP[srow][grp+base+0] = to_tf32(v.x);
            sKP[srow][grp+base+2] = to_tf32(v.y);
            sKP[srow][grp+base+4] = to_tf32(v.z);
            sKP[srow][grp+base+6] = to_tf32(v.w);
        }
    }
    __syncthreads();

    float qf[8][4];
    #pragma unroll
    for (int ks = 0; ks < 8; ks++) {
        float2 a0 = *(const float2*)&sKP[r0][ks*8 + 2*c];
        float2 a1 = *(const float2*)&sKP[r1][ks*8 + 2*c];
        qf[ks][0] = a0.x; qf[ks][1] = a1.x; qf[ks][2] = a0.y; qf[ks][3] = a1.y;
    }

    float of[8][4];
    #pragma unroll
    for (int nt = 0; nt < 8; nt++)
        #pragma unroll
        for (int q = 0; q < 4; q++) of[nt][q] = 0.f;
    float mA = -1e30f, lA = 0.f, mB = -1e30f, lB = 0.f;

    for (int kt = 0; kt < 8; kt++) {
        __syncthreads();
        // ---- stage K and V^T ----
        {
            const float* ksrc = Kp + (size_t)(kt*KT + srow)*1536 + shalf*32;
            const float* vsrc = Vp + (size_t)(kt*KT + srow)*1536 + shalf*32;
            #pragma unroll
            for (int j = 0; j < 8; j++) {
                int k0 = shalf*32 + j*4;
                int grp = k0 & ~7, base = (k0 >> 2) & 1;
                float4 kv4 = *(const float4*)(ksrc + j*4);
                sKP[srow][grp+base+0] = to_tf32(kv4.x);
                sKP[srow][grp+base+2] = to_tf32(kv4.y);
                sKP[srow][grp+base+4] = to_tf32(kv4.z);
                sKP[srow][grp+base+6] = to_tf32(kv4.w);
                float4 vv = *(const float4*)(vsrc + j*4);
                sV[k0+0][sprow] = to_tf32(vv.x);
                sV[k0+1][sprow] = to_tf32(vv.y);
                sV[k0+2][sprow] = to_tf32(vv.z);
                sV[k0+3][sprow] = to_tf32(vv.w);
            }
        }
        __syncthreads();

        // ---- scores ----
        float sc[8][4];
        #pragma unroll
        for (int nt = 0; nt < 8; nt++) {
            sc[nt][0] = sc[nt][1] = sc[nt][2] = sc[nt][3] = 0.f;
        }
        #pragma unroll
        for (int ks = 0; ks < 8; ks++) {
            #pragma unroll
            for (int nt = 0; nt < 8; nt++) {
                const int n0 = nt*8 + g;
                float2 bp = *(const float2*)&sKP[n0][ks*8 + 2*c];
                float bf[2] = {bp.x, bp.y};
                mma_tf32(sc[nt], qf[ks], bf);
            }
        }
        if (Mp) {
            const float* m0p = Mp + (size_t)r0*SS + kt*KT + 2*c;
            const float* m1p = Mp + (size_t)r1*SS + kt*KT + 2*c;
            #pragma unroll
            for (int nt = 0; nt < 8; nt++) {
                float2 u = *(const float2*)(m0p + nt*8);
                float2 v = *(const float2*)(m1p + nt*8);
                sc[nt][0] = sc[nt][0]*0.125f + u.x;
                sc[nt][1] = sc[nt][1]*0.125f + u.y;
                sc[nt][2] = sc[nt][2]*0.125f + v.x;
                sc[nt][3] = sc[nt][3]*0.125f + v.y;
            }
        } else {
            #pragma unroll
            for (int nt = 0; nt < 8; nt++) {
                sc[nt][0] *= 0.125f; sc[nt][1] *= 0.125f;
                sc[nt][2] *= 0.125f; sc[nt][3] *= 0.125f;
            }
        }
        // ---- online softmax ----
        float aMax = -1e30f, bMax = -1e30f;
        #pragma unroll
        for (int nt = 0; nt < 8; nt++) {
            aMax = fmaxf(aMax, fmaxf(sc[nt][0], sc[nt][1]));
            bMax = fmaxf(bMax, fmaxf(sc[nt][2], sc[nt][3]));
        }
        aMax = fmaxf(aMax, __shfl_xor_sync(0xffffffffu, aMax, 1));
        aMax = fmaxf(aMax, __shfl_xor_sync(0xffffffffu, aMax, 2));
        bMax = fmaxf(bMax, __shfl_xor_sync(0xffffffffu, bMax, 1));
        bMax = fmaxf(bMax, __shfl_xor_sync(0xffffffffu, bMax, 2));
        float mnA = fmaxf(mA, aMax), mnB = fmaxf(mB, bMax);
        float alA = __expf(mA - mnA), alB = __expf(mB - mnB);
        mA = mnA; mB = mnB;
        float sumA = 0.f, sumB = 0.f;
        #pragma unroll
        for (int nt = 0; nt < 8; nt++) {
            sc[nt][0] = __expf(sc[nt][0] - mnA); sumA += sc[nt][0];
            sc[nt][1] = __expf(sc[nt][1] - mnA); sumA += sc[nt][1];
            sc[nt][2] = __expf(sc[nt][2] - mnB); sumB += sc[nt][2];
            sc[nt][3] = __expf(sc[nt][3] - mnB); sumB += sc[nt][3];
        }
        sumA += __shfl_xor_sync(0xffffffffu, sumA, 1);
        sumA += __shfl_xor_sync(0xffffffffu, sumA, 2);
        sumB += __shfl_xor_sync(0xffffffffu, sumB, 1);
        sumB += __shfl_xor_sync(0xffffffffu, sumB, 2);
        lA = lA*alA + sumA;
        lB = lB*alB + sumB;
        #pragma unroll
        for (int nt = 0; nt < 8; nt++) {
            of[nt][0] *= alA; of[nt][1] *= alA;
            of[nt][2] *= alB; of[nt][3] *= alB;
        }

        __syncthreads();
        // ---- store P into sKP (own rows only), perm k layout ----
        const int pc0 = perm8(2*c), pc1 = perm8(2*c + 1);
        #pragma unroll
        for (int nt = 0; nt < 8; nt++) {
            const int col0 = nt*8;
            sKP[r0][col0 + pc0] = to_tf32(sc[nt][0]);
            sKP[r0][col0 + pc1] = to_tf32(sc[nt][1]);
            sKP[r1][col0 + pc0] = to_tf32(sc[nt][2]);
            sKP[r1][col0 + pc1] = to_tf32(sc[nt][3]);
        }
        __syncwarp();
        // ---- PV ----
        #pragma unroll
        for (int ks = 0; ks < 8; ks++) {
            float2 a0 = *(const float2*)&sKP[r0][ks*8 + 2*c];
            float2 a1 = *(const float2*)&sKP[r1][ks*8 + 2*c];
            float af[4] = {a0.x, a1.x, a0.y, a1.y};
            #pragma unroll
            for (int nt = 0; nt < 8; nt++) {
                const int n0 = nt*8 + g;
                float2 bp = *(const float2*)&sV[n0][ks*8 + 2*c];
                float bf[2] = {bp.x, bp.y};
                mma_tf32(of[nt], af, bf);
            }
        }
    }

    // ---- epilogue ----
    const float invA = 1.f / lA, invB = 1.f / lB;
    #pragma unroll
    for (int nt = 0; nt < 8; nt++) {
        const int col = nt*8 + 2*c;
        *(float2*)(Op + (size_t)r0*HH + col) =
            make_float2(of[nt][0]*invA, of[nt][1]*invA);
        *(float2*)(Op + (size_t)r1*HH + col) =
            make_float2(of[nt][2]*invB, of[nt][3]*invB);
    }
}

// ---------------- LayerNorm over 512 (+optional residual, +optional gelu) ----------------
__global__ void ln_kernel(const float* __restrict__ in, const float* __restrict__ res,
                          const float* __restrict__ g, const float* __restrict__ be,
                          float* __restrict__ out, int do_gelu)
{
    __shared__ float red[4];
    int row = blockIdx.x, tid = threadIdx.x;
    const float* ip = in + (size_t)row*HH;
    const float* rp = res ? (res + (size_t)row*HH) : nullptr;
    float v[4]; float s = 0.f;
    #pragma unroll
    for (int j = 0; j < 4; j++) {
        float x = ip[tid + 128*j];
        if (rp) x += rp[tid + 128*j];
        v[j] = x; s += x;
    }
    s = warp_sum(s);
    if ((tid & 31) == 0) red[tid >> 5] = s;
    __syncthreads();
    float mean = (red[0]+red[1]+red[2]+red[3]) * (1.f/HH);
    __syncthreads();
    float ss = 0.f;
    #pragma unroll
    for (int j = 0; j < 4; j++) { float d = v[j] - mean; ss += d*d; }
    ss = warp_sum(ss);
    if ((tid & 31) == 0) red[tid >> 5] = ss;
    __syncthreads();
    float var = (red[0]+red[1]+red[2]+red[3]) * (1.f/HH);
    float rs = rsqrtf(var + EPS);
    float* op = out + (size_t)row*HH;
    #pragma unroll
    for (int j = 0; j < 4; j++) {
        int cc = tid + 128*j;
        float y = (v[j] - mean) * rs * g[cc] + be[cc];
        if (do_gelu) y = gelu_exact(y);
        op[cc] = y;
    }
}

// ---------------- mixer: logits(3) -> softmax -> weighted combine ----------------
__global__ void mix_kernel(const float* __restrict__ mact, const float* __restrict__ W2,
                           const float* __restrict__ b2, const float* __restrict__ comb,
                           float* __restrict__ weighted)
{
    __shared__ float sl[3][4];
    __shared__ float smix[3];
    int row = blockIdx.x, tid = threadIdx.x;
    const float* mrow = mact + (size_t)row*HH;
    float l0 = 0.f, l1 = 0.f, l2 = 0.f;
    for (int d = tid; d < HH; d += 128) {
        float m = mrow[d];
        l0 += m * W2[d*3+0];
        l1 += m * W2[d*3+1];
        l2 += m * W2[d*3+2];
    }
    l0 = warp_sum(l0); l1 = warp_sum(l1); l2 = warp_sum(l2);
    int w = tid >> 5;
    if ((tid & 31) == 0) { sl[0][w] = l0; sl[1][w] = l1; sl[2][w] = l2; }
    __syncthreads();
    if (tid == 0) {
        float a0 = sl[0][0]+sl[0][1]+sl[0][2]+sl[0][3] + b2[0];
        float a1 = sl[1][0]+sl[1][1]+sl[1][2]+sl[1][3] + b2[1];
        float a2 = sl[2][0]+sl[2][1]+sl[2][2]+sl[2][3] + b2[2];
        float mx = fmaxf(a0, fmaxf(a1, a2));
        float e0 = expf(a0-mx), e1 = expf(a1-mx), e2 = expf(a2-mx);
        float inv = 1.f / (e0+e1+e2);
        smix[0] = e0*inv; smix[1] = e1*inv; smix[2] = e2*inv;
    }
    __syncthreads();
    float m0 = smix[0], m1 = smix[1], m2 = smix[2];
    const float* crow = comb + (size_t)row*(3*HH);
    float* wrow = weighted + (size_t)row*HH;
    for (int cc = tid; cc < HH; cc += 128)
        wrow[cc] = m0*crow[cc] + m1*crow[HH + cc] + m2*crow[2*HH + cc];
}

// ---------------- launch ----------------
extern "C" void kernel_launch(void* const* d_in, const int* in_sizes, int n_in,
                              void* d_out, int out_size)
{
    const float* x          = (const float*)d_in[0];
    const float* ts         = (const float*)d_in[1];
    const float* enc_W      = (const float*)d_in[2];
    const float* enc_b      = (const float*)d_in[3];
    const float* enc_ln_g   = (const float*)d_in[4];
    const float* enc_ln_b   = (const float*)d_in[5];
    const float* qkv_W      = (const float*)d_in[6];
    const float* qkv_b      = (const float*)d_in[7];
    const float* attn_out_W = (const float*)d_in[8];
    const float* attn_out_b = (const float*)d_in[9];
    const float* mixer_W1   = (const float*)d_in[10];
    const float* mixer_b1   = (const float*)d_in[11];
    const float* mixer_ln_g = (const float*)d_in[12];
    const float* mixer_ln_b = (const float*)d_in[13];
    const float* mixer_W2   = (const float*)d_in[14];
    const float* mixer_b2   = (const float*)d_in[15];
    const float* el_qkv_W   = (const float*)d_in[16];
    const float* el_qkv_b   = (const float*)d_in[17];
    const float* el_out_W   = (const float*)d_in[18];
    const float* el_out_b   = (const float*)d_in[19];
    const float* el_ln1_g   = (const float*)d_in[20];
    const float* el_ln1_b   = (const float*)d_in[21];
    const float* el_ff_W1   = (const float*)d_in[22];
    const float* el_ff_b1   = (const float*)d_in[23];
    const float* el_ff_W2   = (const float*)d_in[24];
    const float* el_ff_b2   = (const float*)d_in[25];
    const float* el_ln2_g   = (const float*)d_in[26];
    const float* el_ln2_b   = (const float*)d_in[27];
    const float* op_W       = (const float*)d_in[28];
    const float* op_b       = (const float*)d_in[29];
    const float* op_ln_g    = (const float*)d_in[30];
    const float* op_ln_b    = (const float*)d_in[31];
    float* out = (float*)d_out;

    float* base = nullptr;
    cudaGetSymbolAddress((void**)&base, g_scratch);
    float* maskv    = base + OFF_MASK;
    float* qkv      = base + OFF_QKV;
    float* attno    = base + OFF_ATTNO;
    float* comb     = base + OFF_COMB;
    float* mact     = base + OFF_MACT;
    float* weighted = base + OFF_WEIGHTED;
    float* sa       = base + OFF_SA;
    float* h1       = base + OFF_H1;
    float* ff       = base + OFF_FF;
    float* ffo      = base + OFF_FFO;
    float* h2       = base + OFF_H2;
    float* opb      = base + OFF_OP;
    float* tab      = base + OFF_TAB;

    // allow 70KB dynamic smem for the gemm kernels (idempotent)
    cudaFuncSetAttribute(gemm_tc2<0>, cudaFuncAttributeMaxDynamicSharedMemorySize, G2_SMEM_BYTES);
    cudaFuncSetAttribute(gemm_tc2<1>, cudaFuncAttributeMaxDynamicSharedMemorySize, G2_SMEM_BYTES);

    // 1. mask tables + fill
    {
        int nwarp = 3*2*TABENT + 3;
        int nblk = (nwarp*32 + 255) / 256;
        tab_kernel<<<nblk, 256>>>(enc_W, enc_b, enc_ln_g, enc_ln_b, tab);
        maskfill_kernel<<<(BSS + 255)/256, 256>>>(ts, tab, maskv);
    }

    // 2. per-timescale QKV (batched over z=3) + fused attention
    gemm_tc2<0><<<dim3(12,16,3), 256, G2_SMEM_BYTES>>>(x, HH, qkv_W, 1536, qkv_b, qkv, 1536, HH,
                                           (size_t)0, (size_t)HH*1536, (size_t)BS*1536, (size_t)1536);
    flash_kernel<<<dim3(8, BB*NHH, 3), 128>>>(qkv, maskv, attno);
    gemm_tc2<0><<<dim3(4,16,3), 256, G2_SMEM_BYTES>>>(attno, HH, attn_out_W, HH, attn_out_b,
                                         comb, 1536, HH,
                                         (size_t)BS*HH, (size_t)HH*HH, (size_t)HH, (size_t)HH);

    // 3. time mixer
    gemm_tc2<0><<<dim3(4,16,1), 256, G2_SMEM_BYTES>>>(comb, 1536, mixer_W1, HH, mixer_b1, mact, HH, 1536,
                                         (size_t)0,(size_t)0,(size_t)0,(size_t)0);
    ln_kernel<<<BS, 128>>>(mact, nullptr, mixer_ln_g, mixer_ln_b, mact, 1);
    mix_kernel<<<BS, 128>>>(mact, mixer_W2, mixer_b2, comb, weighted);

    // 4. transformer encoder layer (post-norm)
    gemm_tc2<0><<<dim3(12,16,1), 256, G2_SMEM_BYTES>>>(weighted, HH, el_qkv_W, 1536, el_qkv_b, qkv, 1536, HH,
                                           (size_t)0,(size_t)0,(size_t)0,(size_t)0);
    flash_kernel<<<dim3(8, BB*NHH, 1), 128>>>(qkv, nullptr, attno);
    gemm_tc2<0><<<dim3(4,16,1), 256, G2_SMEM_BYTES>>>(attno, HH, el_out_W, HH, el_out_b, sa, HH, HH,
                                         (size_t)0,(size_t)0,(size_t)0,(size_t)0);
    ln_kernel<<<BS, 128>>>(sa, weighted, el_ln1_g, el_ln1_b, h1, 0);
    gemm_tc2<1><<<dim3(16,16,1), 256, G2_SMEM_BYTES>>>(h1, HH, el_ff_W1, 2048, el_ff_b1, ff, 2048, HH,
                                           (size_t)0,(size_t)0,(size_t)0,(size_t)0);
    gemm_tc2<0><<<dim3(4,16,1), 256, G2_SMEM_BYTES>>>(ff, 2048, el_ff_W2, HH, el_ff_b2, ffo, HH, 2048,
                                         (size_t)0,(size_t)0,(size_t)0,(size_t)0);
    ln_kernel<<<BS, 128>>>(ffo, h1, el_ln2_g, el_ln2_b, h2, 0);

    // 5. output projection + LN
    gemm_tc2<0><<<dim3(4,16,1), 256, G2_SMEM_BYTES>>>(h2, HH, op_W, HH, op_b, opb, HH, HH,
                                         (size_t)0,(size_t)0,(size_t)0,(size_t)0);
    ln_kernel<<<BS, 128>>>(opb, nullptr, op_ln_g, op_ln_b, out, 0);
}

// round 6
// speedup vs baseline: 1.0348x; 1.0348x over previous
#include <cuda_runtime.h>
#include <math.h>
#include <stdint.h>

// ---------------- problem constants ----------------
#define BB   4
#define SS   512
#define HH   512
#define NHH  8
#define TT   3
#define DHH  64
#define DTS  170
#define BS   (BB*SS)             // 2048
#define BSS  (BB*SS*SS)          // 1,048,576
#define EPS  1e-5f

// mask lookup table
#define NTAB   4096
#define M0MAX  5.6400f
#define TABENT (NTAB+1)
#define TABSZ  (3*2*TABENT + 3)

// ---------------- scratch layout (floats) ----------------
#define OFF_MASK     ((size_t)0)                         // 3 * BSS
#define OFF_QKV      (OFF_MASK + (size_t)3*BSS)          // 3 * BS * 1536
#define OFF_ATTNO    (OFF_QKV + (size_t)3*BS*1536)       // 3 * BS * HH
#define OFF_COMB     (OFF_ATTNO + (size_t)3*BS*HH)       // BS*1536
#define OFF_MACT     (OFF_COMB + (size_t)BS*1536)
#define OFF_WEIGHTED (OFF_MACT + (size_t)BS*HH)
#define OFF_SA       (OFF_WEIGHTED + (size_t)BS*HH)
#define OFF_H1       (OFF_SA + (size_t)BS*HH)
#define OFF_FF       (OFF_H1 + (size_t)BS*HH)            // BS*2048
#define OFF_FFO      (OFF_FF + (size_t)BS*2048)
#define OFF_H2       (OFF_FFO + (size_t)BS*HH)
#define OFF_OP       (OFF_H2 + (size_t)BS*HH)
#define OFF_TAB      (OFF_OP + (size_t)BS*HH)
#define SCRATCH_FLOATS (OFF_TAB + (size_t)TABSZ)

__device__ float g_scratch[SCRATCH_FLOATS];

// ---------------- helpers ----------------
__device__ __forceinline__ float gelu_exact(float x) {
    return 0.5f * x * (1.0f + erff(x * 0.70710678118654752f));
}
__device__ __forceinline__ float warp_sum(float x) {
    #pragma unroll
    for (int o = 16; o > 0; o >>= 1) x += __shfl_xor_sync(0xffffffffu, x, o);
    return x;
}
__device__ __forceinline__ float to_tf32(float x) {
    uint32_t u;
    asm("cvt.rna.tf32.f32 %0, %1;" : "=r"(u) : "f"(x));
    return __uint_as_float(u);
}
__device__ __forceinline__ void mma_tf32(float* c, const float* a, const float* b) {
    asm volatile(
        "mma.sync.aligned.m16n8k8.row.col.f32.tf32.tf32.f32 "
        "{%0,%1,%2,%3}, {%4,%5,%6,%7}, {%8,%9}, {%0,%1,%2,%3};\n"
        : "+f"(c[0]), "+f"(c[1]), "+f"(c[2]), "+f"(c[3])
        : "r"(__float_as_uint(a[0])), "r"(__float_as_uint(a[1])),
          "r"(__float_as_uint(a[2])), "r"(__float_as_uint(a[3])),
          "r"(__float_as_uint(b[0])), "r"(__float_as_uint(b[1])));
}
__device__ __forceinline__ void cp_async16(uint32_t dst, const void* src) {
    asm volatile("cp.async.ca.shared.global [%0], [%1], 16;\n" :: "r"(dst), "l"(src));
}
#define CP_COMMIT() asm volatile("cp.async.commit_group;\n" ::: "memory")
#define CP_WAIT0()  asm volatile("cp.async.wait_group 0;\n" ::: "memory")

// ---------------- mask table build ----------------
__global__ void tab_kernel(const float* __restrict__ enc_W,
                           const float* __restrict__ enc_b,
                           const float* __restrict__ enc_g,
                           const float* __restrict__ enc_be,
                           float* __restrict__ tab)
{
    int w = (blockIdx.x * blockDim.x + threadIdx.x) >> 5;
    int lane = threadIdx.x & 31;
    const int NE = 3 * 2 * TABENT;
    if (w >= NE + 3) return;
    int i; float dir, mag;
    if (w < NE) {
        i = w / (2 * TABENT);
        int r = w - i * (2 * TABENT);
        int d = r / TABENT;
        int j = r - d * TABENT;
        dir = d ? 1.f : -1.f;
        float m0 = (float)j * (M0MAX / NTAB);
        float sc = (i == 0) ? 1.f : ((i == 1) ? 0.1f : 0.01f);
        mag = m0 * sc;
    } else {
        i = w - NE; dir = 0.f; mag = 0.f;
    }
    const float* W0 = enc_W + (size_t)(i*2+0)*DTS;
    const float* W1 = enc_W + (size_t)(i*2+1)*DTS;
    const float* bb = enc_b + (size_t)i*DTS;
    const float* gg = enc_g + (size_t)i*DTS;
    const float* be = enc_be + (size_t)i*DTS;

    float e[6];
    float s = 0.f, ss = 0.f;
    #pragma unroll
    for (int j2 = 0; j2 < 6; j2++) {
        int d = lane + 32*j2;
        float v = 0.f;
        if (d < DTS) v = dir*W0[d] + mag*W1[d] + bb[d];
        e[j2] = v; s += v; ss += v*v;
    }
    s  = warp_sum(s);
    ss = warp_sum(ss);
    float mean = s * (1.f/DTS);
    float var  = ss * (1.f/DTS) - mean*mean;
    float rs = rsqrtf(var + EPS);
    float gs = 0.f;
    #pragma unroll
    for (int j2 = 0; j2 < 6; j2++) {
        int d = lane + 32*j2;
        if (d < DTS) {
            float y = (e[j2] - mean) * rs * gg[d] + be[d];
            gs += gelu_exact(y);
        }
    }
    gs = warp_sum(gs);
    if (lane == 0) tab[w] = gs * (1.f/DTS);
}

// ---------------- mask fill via table interpolation ----------------
__global__ void maskfill_kernel(const float* __restrict__ ts,
                                const float* __restrict__ tab,
                                float* __restrict__ masks)
{
    int idx = blockIdx.x * blockDim.x + threadIdx.x;
    if (idx >= BSS) return;
    int b = idx >> 18;
    int q = (idx >> 9) & 511;
    int k = idx & 511;
    float dt = ts[(b << 9) + q] - ts[(b << 9) + k];
    if (dt == 0.f) {
        #pragma unroll
        for (int i = 0; i < TT; i++)
            masks[(size_t)i*BSS + idx] = tab[3*2*TABENT + i];
    } else {
        int d = dt > 0.f ? 1 : 0;
        float m0 = log1pf(fabsf(dt) * (1.f/3600.f));
        float t = m0 * ((float)NTAB / M0MAX);
        t = fminf(t, (float)NTAB - 1e-3f);
        int j = (int)t;
        float f = t - (float)j;
        #pragma unroll
        for (int i = 0; i < TT; i++) {
            const float* tb = tab + (size_t)(i*2 + d) * TABENT;
            float a = tb[j];
            masks[(size_t)i*BSS + idx] = a + f * (tb[j+1] - a);
        }
    }
}

// ---------------- tf32 tensor-core GEMM (dense NN, R4 proven version) ----------------
template<int BN, int GELU>
__global__ __launch_bounds__(256)
void gemm_tc(const float* __restrict__ A0, int lda,
             const float* __restrict__ B0, int ldb,
             const float* __restrict__ bias0,
             float* __restrict__ C0, int ldc, int K,
             size_t sAz, size_t sBz, size_t sCz, size_t sbz)
{
    constexpr int BM = 128;
    constexpr int BK = 16;
    constexpr int WN = BN / 4;
    constexpr int NT2 = WN / 8;

    __shared__ float sA[2][BM][BK + 4];
    __shared__ float sB[2][BK][BN + 8];

    const int tid  = threadIdx.x;
    const int lane = tid & 31;
    const int warp = tid >> 5;
    const int wm = warp & 1;
    const int wn = warp >> 1;
    const int g = lane >> 2;
    const int c = lane & 3;

    const int bm = blockIdx.y * BM;
    const int bn = blockIdx.x * BN;
    const int z  = blockIdx.z;

    const float* A = A0 + (size_t)z * sAz;
    const float* B = B0 + (size_t)z * sBz;
    const float* bias = bias0 + (size_t)z * sbz;
    float* C = C0 + (size_t)z * sCz;

    const int ar = tid >> 2;
    const int ac = (tid & 3) * 4;
    const float* aP  = A + (size_t)(bm + ar)*lda + ac;
    const float* aP2 = aP + (size_t)64*lda;

    int bkr, bnc;
    if (BN == 128) { bkr = tid >> 5; bnc = (tid & 31) * 4; }
    else           { bkr = tid >> 4; bnc = (tid & 15) * 4; }

    float acc[4][NT2][4];
    #pragma unroll
    for (int i = 0; i < 4; i++)
        #pragma unroll
        for (int j = 0; j < NT2; j++)
            #pragma unroll
            for (int q = 0; q < 4; q++) acc[i][j][q] = 0.f;

    auto storeA = [&](int buf, float4 x, float4 y) {
        sA[buf][ar][ac+0] = to_tf32(x.x); sA[buf][ar][ac+1] = to_tf32(x.y);
        sA[buf][ar][ac+2] = to_tf32(x.z); sA[buf][ar][ac+3] = to_tf32(x.w);
        sA[buf][ar+64][ac+0] = to_tf32(y.x); sA[buf][ar+64][ac+1] = to_tf32(y.y);
        sA[buf][ar+64][ac+2] = to_tf32(y.z); sA[buf][ar+64][ac+3] = to_tf32(y.w);
    };
    auto loadB = [&](int k0, float4& x, float4& y) {
        const float* p = B + (size_t)(k0 + bkr)*ldb + bn + bnc;
        x = *(const float4*)p;
        if (BN == 128) y = *(const float4*)(p + (size_t)8*ldb);
    };
    auto storeB = [&](int buf, float4 x, float4 y) {
        sB[buf][bkr][bnc+0] = to_tf32(x.x); sB[buf][bkr][bnc+1] = to_tf32(x.y);
        sB[buf][bkr][bnc+2] = to_tf32(x.z); sB[buf][bkr][bnc+3] = to_tf32(x.w);
        if (BN == 128) {
            sB[buf][bkr+8][bnc+0] = to_tf32(y.x); sB[buf][bkr+8][bnc+1] = to_tf32(y.y);
            sB[buf][bkr+8][bnc+2] = to_tf32(y.z); sB[buf][bkr+8][bnc+3] = to_tf32(y.w);
        }
    };

    const int nstage = K / BK;
    float4 pa0, pa1, pb0, pb1;

    pa0 = *(const float4*)(aP);
    pa1 = *(const float4*)(aP2);
    loadB(0, pb0, pb1);
    storeA(0, pa0, pa1);
    storeB(0, pb0, pb1);
    __syncthreads();

    for (int s = 0; s < nstage; s++) {
        const int cur = s & 1;
        const bool more = (s + 1 < nstage);
        if (more) {
            const int k0 = (s + 1) * BK;
            pa0 = *(const float4*)(aP + k0);
            pa1 = *(const float4*)(aP2 + k0);
            loadB(k0, pb0, pb1);
        }
        #pragma unroll
        for (int kk = 0; kk < 2; kk++) {
            const int kb = kk * 8;
            float af[4][4];
            #pragma unroll
            for (int mt = 0; mt < 4; mt++) {
                const int r0 = wm*64 + mt*16 + g;
                af[mt][0] = sA[cur][r0][kb + c];
                af[mt][1] = sA[cur][r0 + 8][kb + c];
                af[mt][2] = sA[cur][r0][kb + c + 4];
                af[mt][3] = sA[cur][r0 + 8][kb + c + 4];
            }
            float bf[NT2][2];
            #pragma unroll
            for (int nt = 0; nt < NT2; nt++) {
                const int n0 = wn*WN + nt*8 + g;
                bf[nt][0] = sB[cur][kb + c][n0];
                bf[nt][1] = sB[cur][kb + c + 4][n0];
            }
            #pragma unroll
            for (int mt = 0; mt < 4; mt++)
                #pragma unroll
                for (int nt = 0; nt < NT2; nt++)
                    mma_tf32(acc[mt][nt], af[mt], bf[nt]);
        }
        if (more) {
            const int nxt = cur ^ 1;
            storeA(nxt, pa0, pa1);
            storeB(nxt, pb0, pb1);
        }
        __syncthreads();
    }

    #pragma unroll
    for (int mt = 0; mt < 4; mt++) {
        const int row = bm + wm*64 + mt*16 + g;
        #pragma unroll
        for (int nt = 0; nt < NT2; nt++) {
            const int col = bn + wn*WN + nt*8 + c*2;
            float2 bb = *(const float2*)(bias + col);
            float v00 = acc[mt][nt][0] + bb.x, v01 = acc[mt][nt][1] + bb.y;
            float v10 = acc[mt][nt][2] + bb.x, v11 = acc[mt][nt][3] + bb.y;
            if (GELU) {
                v00 = gelu_exact(v00); v01 = gelu_exact(v01);
                v10 = gelu_exact(v10); v11 = gelu_exact(v11);
            }
            *(float2*)(C + (size_t)row*ldc + col) = make_float2(v00, v01);
            *(float2*)(C + (size_t)(row+8)*ldc + col) = make_float2(v10, v11);
        }
    }
}

// ---------------- fused flash attention v2: cp.async double-buffered, P in regs ----------------
// grid (S/64, B*NH, T). 128 threads (4 warps). Raw f32 in smem; cvt at fragment load.
#define QT 64
#define KT 64
#define FS 68                         // smem row stride (floats): conflict-free patterns
#define FTILE (64*FS)                 // 4352 floats per tile buffer
#define FLASH_SMEM_BYTES (4*FTILE*4)  // 2 K buffers + 2 V buffers

__global__ __launch_bounds__(128, 3)
void flash_kernel(const float* __restrict__ qkvb,
                  const float* __restrict__ maskb,
                  float* __restrict__ attnob)
{
    extern __shared__ float fsm[];
    // layout: K buf0 | K buf1 | V buf0 | V buf1

    const int qt = blockIdx.x;
    const int bh = blockIdx.y;
    const int t  = blockIdx.z;
    const int b = bh >> 3, h = bh & 7;
    const int tid = threadIdx.x;
    const int lane = tid & 31, warp = tid >> 5;
    const int g = lane >> 2, c = lane & 3;
    const int r0 = warp*16 + g, r1 = r0 + 8;

    const float* Qp = qkvb + (size_t)t*BS*1536 + (size_t)b*SS*1536 + h*DHH;
    const float* Kp = Qp + HH;
    const float* Vp = Qp + 2*HH;
    const float* Mp = maskb ? (maskb + (size_t)t*BSS + (size_t)b*SS*SS + (size_t)(qt*QT)*SS)
                            : nullptr;
    float* Op = attnob + (size_t)t*BS*HH + (size_t)b*SS*HH + h*DHH + (size_t)(qt*QT)*HH;

    // staging: thread covers row srow, half of the 64-float row (8 x 16B chunks)
    const int srow = tid >> 1;
    const int shalf = (tid & 1) * 32;
    const uint32_t smemBase = (uint32_t)__cvta_generic_to_shared(fsm);
    const uint32_t rowOff = (uint32_t)((srow*FS + shalf) * 4);

    auto stageKV = [&](int tile, int buf) {
        const float* ksrc = Kp + (size_t)(tile*KT + srow)*1536 + shalf;
        const float* vsrc = Vp + (size_t)(tile*KT + srow)*1536 + shalf;
        uint32_t kdst = smemBase + (uint32_t)(buf*FTILE*4) + rowOff;
        uint32_t vdst = smemBase + (uint32_t)((2*FTILE + buf*FTILE)*4) + rowOff;
        #pragma unroll
        for (int j = 0; j < 8; j++) {
            cp_async16(kdst + j*16, ksrc + j*4);
            cp_async16(vdst + j*16, vsrc + j*4);
        }
    };

    // prologue: Q -> K buf1 region; K0,V0 -> buf0
    {
        const float* qsrc = Qp + (size_t)(qt*QT + srow)*1536 + shalf;
        uint32_t qdst = smemBase + (uint32_t)(FTILE*4) + rowOff;
        #pragma unroll
        for (int j = 0; j < 8; j++) cp_async16(qdst + j*16, qsrc + j*4);
        stageKV(0, 0);
        CP_COMMIT();
        CP_WAIT0();
        __syncthreads();
    }

    // load Q fragments (from K buf1 region), convert to tf32
    float qf[8][4];
    {
        const float* sQ = fsm + FTILE;
        #pragma unroll
        for (int ks = 0; ks < 8; ks++) {
            qf[ks][0] = to_tf32(sQ[r0*FS + ks*8 + c]);
            qf[ks][1] = to_tf32(sQ[r1*FS + ks*8 + c]);
            qf[ks][2] = to_tf32(sQ[r0*FS + ks*8 + c + 4]);
            qf[ks][3] = to_tf32(sQ[r1*FS + ks*8 + c + 4]);
        }
    }
    __syncthreads();   // all warps done reading Q before kt=0 prefetches into buf1

    float of[8][4];
    #pragma unroll
    for (int nt = 0; nt < 8; nt++)
        #pragma unroll
        for (int q = 0; q < 4; q++) of[nt][q] = 0.f;
    float mA = -1e30f, lA = 0.f, mB = -1e30f, lB = 0.f;

    for (int kt = 0; kt < 8; kt++) {
        const int cur = kt & 1;
        const bool more = (kt + 1 < 8);
        if (more) { stageKV(kt + 1, cur ^ 1); CP_COMMIT(); }

        const float* sK = fsm + cur*FTILE;
        const float* sV = fsm + 2*FTILE + cur*FTILE;

        // ---- scores: Q @ K^T ----
        float sc[8][4];
        #pragma unroll
        for (int nt = 0; nt < 8; nt++)
            sc[nt][0] = sc[nt][1] = sc[nt][2] = sc[nt][3] = 0.f;
        #pragma unroll
        for (int ks = 0; ks < 8; ks++) {
            #pragma unroll
            for (int nt = 0; nt < 8; nt++) {
                const float* kp = sK + (nt*8 + g)*FS + ks*8;
                float bf[2] = { to_tf32(kp[c]), to_tf32(kp[c + 4]) };
                mma_tf32(sc[nt], qf[ks], bf);
            }
        }
        // scale + mask
        if (Mp) {
            const float* m0p = Mp + (size_t)r0*SS + kt*KT + 2*c;
            const float* m1p = Mp + (size_t)r1*SS + kt*KT + 2*c;
            #pragma unroll
            for (int nt = 0; nt < 8; nt++) {
                float2 u = *(const float2*)(m0p + nt*8);
                float2 v = *(const float2*)(m1p + nt*8);
                sc[nt][0] = sc[nt][0]*0.125f + u.x;
                sc[nt][1] = sc[nt][1]*0.125f + u.y;
                sc[nt][2] = sc[nt][2]*0.125f + v.x;
                sc[nt][3] = sc[nt][3]*0.125f + v.y;
            }
        } else {
            #pragma unroll
            for (int nt = 0; nt < 8; nt++) {
                sc[nt][0] *= 0.125f; sc[nt][1] *= 0.125f;
                sc[nt][2] *= 0.125f; sc[nt][3] *= 0.125f;
            }
        }
        // ---- online softmax ----
        float aMax = -1e30f, bMax = -1e30f;
        #pragma unroll
        for (int nt = 0; nt < 8; nt++) {
            aMax = fmaxf(aMax, fmaxf(sc[nt][0], sc[nt][1]));
            bMax = fmaxf(bMax, fmaxf(sc[nt][2], sc[nt][3]));
        }
        aMax = fmaxf(aMax, __shfl_xor_sync(0xffffffffu, aMax, 1));
        aMax = fmaxf(aMax, __shfl_xor_sync(0xffffffffu, aMax, 2));
        bMax = fmaxf(bMax, __shfl_xor_sync(0xffffffffu, bMax, 1));
        bMax = fmaxf(bMax, __shfl_xor_sync(0xffffffffu, bMax, 2));
        float mnA = fmaxf(mA, aMax), mnB = fmaxf(mB, bMax);
        float alA = __expf(mA - mnA), alB = __expf(mB - mnB);
        mA = mnA; mB = mnB;
        float sumA = 0.f, sumB = 0.f;
        #pragma unroll
        for (int nt = 0; nt < 8; nt++) {
            sc[nt][0] = __expf(sc[nt][0] - mnA); sumA += sc[nt][0];
            sc[nt][1] = __expf(sc[nt][1] - mnA); sumA += sc[nt][1];
            sc[nt][2] = __expf(sc[nt][2] - mnB); sumB += sc[nt][2];
            sc[nt][3] = __expf(sc[nt][3] - mnB); sumB += sc[nt][3];
        }
        sumA += __shfl_xor_sync(0xffffffffu, sumA, 1);
        sumA += __shfl_xor_sync(0xffffffffu, sumA, 2);
        sumB += __shfl_xor_sync(0xffffffffu, sumB, 1);
        sumB += __shfl_xor_sync(0xffffffffu, sumB, 2);
        lA = lA*alA + sumA;
        lB = lB*alB + sumB;
        #pragma unroll
        for (int nt = 0; nt < 8; nt++) {
            of[nt][0] *= alA; of[nt][1] *= alA;
            of[nt][2] *= alB; of[nt][3] *= alB;
        }

        // ---- PV: P accumulators used directly as A-fragments (perm8 kv space) ----
        // A-frag (kperm c, c+4) = real kv (2c, 2c+1) = {sc[ks][0], sc[ks][2], sc[ks][1], sc[ks][3]}
        #pragma unroll
        for (int ks = 0; ks < 8; ks++) {
            float af[4] = { to_tf32(sc[ks][0]), to_tf32(sc[ks][2]),
                            to_tf32(sc[ks][1]), to_tf32(sc[ks][3]) };
            #pragma unroll
            for (int nt = 0; nt < 8; nt++) {
                const float* vp = sV + (ks*8 + 2*c)*FS + nt*8 + g;
                float bf[2] = { to_tf32(vp[0]), to_tf32(vp[FS]) };
                mma_tf32(of[nt], af, bf);
            }
        }

        if (more) { CP_WAIT0(); }
        __syncthreads();
    }

    // ---- epilogue ----
    const float invA = 1.f / lA, invB = 1.f / lB;
    #pragma unroll
    for (int nt = 0; nt < 8; nt++) {
        const int col = nt*8 + 2*c;
        *(float2*)(Op + (size_t)r0*HH + col) =
            make_float2(of[nt][0]*invA, of[nt][1]*invA);
        *(float2*)(Op + (size_t)r1*HH + col) =
            make_float2(of[nt][2]*invB, of[nt][3]*invB);
    }
}

// ---------------- LayerNorm over 512 (+optional residual, +optional gelu) ----------------
__global__ void ln_kernel(const float* __restrict__ in, const float* __restrict__ res,
                          const float* __restrict__ g, const float* __restrict__ be,
                          float* __restrict__ out, int do_gelu)
{
    __shared__ float red[4];
    int row = blockIdx.x, tid = threadIdx.x;
    const float* ip = in + (size_t)row*HH;
    const float* rp = res ? (res + (size_t)row*HH) : nullptr;
    float v[4]; float s = 0.f;
    #pragma unroll
    for (int j = 0; j < 4; j++) {
        float x = ip[tid + 128*j];
        if (rp) x += rp[tid + 128*j];
        v[j] = x; s += x;
    }
    s = warp_sum(s);
    if ((tid & 31) == 0) red[tid >> 5] = s;
    __syncthreads();
    float mean = (red[0]+red[1]+red[2]+red[3]) * (1.f/HH);
    __syncthreads();
    float ss = 0.f;
    #pragma unroll
    for (int j = 0; j < 4; j++) { float d = v[j] - mean; ss += d*d; }
    ss = warp_sum(ss);
    if ((tid & 31) == 0) red[tid >> 5] = ss;
    __syncthreads();
    float var = (red[0]+red[1]+red[2]+red[3]) * (1.f/HH);
    float rs = rsqrtf(var + EPS);
    float* op = out + (size_t)row*HH;
    #pragma unroll
    for (int j = 0; j < 4; j++) {
        int cc = tid + 128*j;
        float y = (v[j] - mean) * rs * g[cc] + be[cc];
        if (do_gelu) y = gelu_exact(y);
        op[cc] = y;
    }
}

// ---------------- mixer: logits(3) -> softmax -> weighted combine ----------------
__global__ void mix_kernel(const float* __restrict__ mact, const float* __restrict__ W2,
                           const float* __restrict__ b2, const float* __restrict__ comb,
                           float* __restrict__ weighted)
{
    __shared__ float sl[3][4];
    __shared__ float smix[3];
    int row = blockIdx.x, tid = threadIdx.x;
    const float* mrow = mact + (size_t)row*HH;
    float l0 = 0.f, l1 = 0.f, l2 = 0.f;
    for (int d = tid; d < HH; d += 128) {
        float m = mrow[d];
        l0 += m * W2[d*3+0];
        l1 += m * W2[d*3+1];
        l2 += m * W2[d*3+2];
    }
    l0 = warp_sum(l0); l1 = warp_sum(l1); l2 = warp_sum(l2);
    int w = tid >> 5;
    if ((tid & 31) == 0) { sl[0][w] = l0; sl[1][w] = l1; sl[2][w] = l2; }
    __syncthreads();
    if (tid == 0) {
        float a0 = sl[0][0]+sl[0][1]+sl[0][2]+sl[0][3] + b2[0];
        float a1 = sl[1][0]+sl[1][1]+sl[1][2]+sl[1][3] + b2[1];
        float a2 = sl[2][0]+sl[2][1]+sl[2][2]+sl[2][3] + b2[2];
        float mx = fmaxf(a0, fmaxf(a1, a2));
        float e0 = expf(a0-mx), e1 = expf(a1-mx), e2 = expf(a2-mx);
        float inv = 1.f / (e0+e1+e2);
        smix[0] = e0*inv; smix[1] = e1*inv; smix[2] = e2*inv;
    }
    __syncthreads();
    float m0 = smix[0], m1 = smix[1], m2 = smix[2];
    const float* crow = comb + (size_t)row*(3*HH);
    float* wrow = weighted + (size_t)row*HH;
    for (int cc = tid; cc < HH; cc += 128)
        wrow[cc] = m0*crow[cc] + m1*crow[HH + cc] + m2*crow[2*HH + cc];
}

// ---------------- launch ----------------
extern "C" void kernel_launch(void* const* d_in, const int* in_sizes, int n_in,
                              void* d_out, int out_size)
{
    const float* x          = (const float*)d_in[0];
    const float* ts         = (const float*)d_in[1];
    const float* enc_W      = (const float*)d_in[2];
    const float* enc_b      = (const float*)d_in[3];
    const float* enc_ln_g   = (const float*)d_in[4];
    const float* enc_ln_b   = (const float*)d_in[5];
    const float* qkv_W      = (const float*)d_in[6];
    const float* qkv_b      = (const float*)d_in[7];
    const float* attn_out_W = (const float*)d_in[8];
    const float* attn_out_b = (const float*)d_in[9];
    const float* mixer_W1   = (const float*)d_in[10];
    const float* mixer_b1   = (const float*)d_in[11];
    const float* mixer_ln_g = (const float*)d_in[12];
    const float* mixer_ln_b = (const float*)d_in[13];
    const float* mixer_W2   = (const float*)d_in[14];
    const float* mixer_b2   = (const float*)d_in[15];
    const float* el_qkv_W   = (const float*)d_in[16];
    const float* el_qkv_b   = (const float*)d_in[17];
    const float* el_out_W   = (const float*)d_in[18];
    const float* el_out_b   = (const float*)d_in[19];
    const float* el_ln1_g   = (const float*)d_in[20];
    const float* el_ln1_b   = (const float*)d_in[21];
    const float* el_ff_W1   = (const float*)d_in[22];
    const float* el_ff_b1   = (const float*)d_in[23];
    const float* el_ff_W2   = (const float*)d_in[24];
    const float* el_ff_b2   = (const float*)d_in[25];
    const float* el_ln2_g   = (const float*)d_in[26];
    const float* el_ln2_b   = (const float*)d_in[27];
    const float* op_W       = (const float*)d_in[28];
    const float* op_b       = (const float*)d_in[29];
    const float* op_ln_g    = (const float*)d_in[30];
    const float* op_ln_b    = (const float*)d_in[31];
    float* out = (float*)d_out;

    float* base = nullptr;
    cudaGetSymbolAddress((void**)&base, g_scratch);
    float* maskv    = base + OFF_MASK;
    float* qkv      = base + OFF_QKV;
    float* attno    = base + OFF_ATTNO;
    float* comb     = base + OFF_COMB;
    float* mact     = base + OFF_MACT;
    float* weighted = base + OFF_WEIGHTED;
    float* sa       = base + OFF_SA;
    float* h1       = base + OFF_H1;
    float* ff       = base + OFF_FF;
    float* ffo      = base + OFF_FFO;
    float* h2       = base + OFF_H2;
    float* opb      = base + OFF_OP;
    float* tab      = base + OFF_TAB;

    cudaFuncSetAttribute(flash_kernel, cudaFuncAttributeMaxDynamicSharedMemorySize, FLASH_SMEM_BYTES);

    // 1. mask tables + fill
    {
        int nwarp = 3*2*TABENT + 3;
        int nblk = (nwarp*32 + 255) / 256;
        tab_kernel<<<nblk, 256>>>(enc_W, enc_b, enc_ln_g, enc_ln_b, tab);
        maskfill_kernel<<<(BSS + 255)/256, 256>>>(ts, tab, maskv);
    }

    // 2. per-timescale QKV (batched over z=3) + fused attention
    gemm_tc<128,0><<<dim3(12,16,3), 256>>>(x, HH, qkv_W, 1536, qkv_b, qkv, 1536, HH,
                                           (size_t)0, (size_t)HH*1536, (size_t)BS*1536, (size_t)1536);
    flash_kernel<<<dim3(8, BB*NHH, 3), 128, FLASH_SMEM_BYTES>>>(qkv, maskv, attno);
    gemm_tc<64,0><<<dim3(8,16,3), 256>>>(attno, HH, attn_out_W, HH, attn_out_b,
                                         comb, 1536, HH,
                                         (size_t)BS*HH, (size_t)HH*HH, (size_t)HH, (size_t)HH);

    // 3. time mixer
    gemm_tc<64,0><<<dim3(8,16,1), 256>>>(comb, 1536, mixer_W1, HH, mixer_b1, mact, HH, 1536,
                                         (size_t)0,(size_t)0,(size_t)0,(size_t)0);
    ln_kernel<<<BS, 128>>>(mact, nullptr, mixer_ln_g, mixer_ln_b, mact, 1);
    mix_kernel<<<BS, 128>>>(mact, mixer_W2, mixer_b2, comb, weighted);

    // 4. transformer encoder layer (post-norm)
    gemm_tc<128,0><<<dim3(12,16,1), 256>>>(weighted, HH, el_qkv_W, 1536, el_qkv_b, qkv, 1536, HH,
                                           (size_t)0,(size_t)0,(size_t)0,(size_t)0);
    flash_kernel<<<dim3(8, BB*NHH, 1), 128, FLASH_SMEM_BYTES>>>(qkv, nullptr, attno);
    gemm_tc<64,0><<<dim3(8,16,1), 256>>>(attno, HH, el_out_W, HH, el_out_b, sa, HH, HH,
                                         (size_t)0,(size_t)0,(size_t)0,(size_t)0);
    ln_kernel<<<BS, 128>>>(sa, weighted, el_ln1_g, el_ln1_b, h1, 0);
    gemm_tc<128,1><<<dim3(16,16,1), 256>>>(h1, HH, el_ff_W1, 2048, el_ff_b1, ff, 2048, HH,
                                           (size_t)0,(size_t)0,(size_t)0,(size_t)0);
    gemm_tc<64,0><<<dim3(8,16,1), 256>>>(ff, 2048, el_ff_W2, HH, el_ff_b2, ffo, HH, 2048,
                                         (size_t)0,(size_t)0,(size_t)0,(size_t)0);
    ln_kernel<<<BS, 128>>>(ffo, h1, el_ln2_g, el_ln2_b, h2, 0);

    // 5. output projection + LN
    gemm_tc<64,0><<<dim3(8,16,1), 256>>>(h2, HH, op_W, HH, op_b, opb, HH, HH,
                                         (size_t)0,(size_t)0,(size_t)0,(size_t)0);
    ln_kernel<<<BS, 128>>>(opb, nullptr, op_ln_g, op_ln_b, out, 0);
}

// round 8
// speedup vs baseline: 1.0986x; 1.0617x over previous
#include <cuda_runtime.h>
#include <cuda_fp16.h>
#include <math.h>
#include <stdint.h>

// ---------------- problem constants ----------------
#define BB   4
#define SS   512
#define HH   512
#define NHH  8
#define TT   3
#define DHH  64
#define DTS  170
#define BS   (BB*SS)             // 2048
#define BSS  (BB*SS*SS)          // 1,048,576
#define EPS  1e-5f

// mask lookup table
#define NTAB   4096
#define M0MAX  5.6400f
#define TABENT (NTAB+1)
#define TABSZ  (3*2*TABENT + 3)

// ---------------- scratch layout (floats) ----------------
#define OFF_MASK     ((size_t)0)                         // 3 * BSS
#define OFF_QKV      (OFF_MASK + (size_t)3*BSS)          // 3 * BS * 1536
#define OFF_ATTNO    (OFF_QKV + (size_t)3*BS*1536)       // 3 * BS * HH
#define OFF_COMB     (OFF_ATTNO + (size_t)3*BS*HH)       // BS*1536
#define OFF_MACT     (OFF_COMB + (size_t)BS*1536)
#define OFF_WEIGHTED (OFF_MACT + (size_t)BS*HH)
#define OFF_SA       (OFF_WEIGHTED + (size_t)BS*HH)
#define OFF_H1       (OFF_SA + (size_t)BS*HH)
#define OFF_FF       (OFF_H1 + (size_t)BS*HH)            // BS*2048
#define OFF_FFO      (OFF_FF + (size_t)BS*2048)
#define OFF_H2       (OFF_FFO + (size_t)BS*HH)
#define OFF_OP       (OFF_H2 + (size_t)BS*HH)
#define OFF_TAB      (OFF_OP + (size_t)BS*HH)
#define SCRATCH_FLOATS (OFF_TAB + (size_t)TABSZ)

__device__ float g_scratch[SCRATCH_FLOATS];

// ---------------- helpers ----------------
__device__ __forceinline__ float gelu_exact(float x) {
    return 0.5f * x * (1.0f + erff(x * 0.70710678118654752f));
}
__device__ __forceinline__ float warp_sum(float x) {
    #pragma unroll
    for (int o = 16; o > 0; o >>= 1) x += __shfl_xor_sync(0xffffffffu, x, o);
    return x;
}
__device__ __forceinline__ float to_tf32(float x) {
    uint32_t u;
    asm("cvt.rna.tf32.f32 %0, %1;" : "=r"(u) : "f"(x));
    return __uint_as_float(u);
}
__device__ __forceinline__ void mma_tf32(float* c, const float* a, const float* b) {
    asm volatile(
        "mma.sync.aligned.m16n8k8.row.col.f32.tf32.tf32.f32 "
        "{%0,%1,%2,%3}, {%4,%5,%6,%7}, {%8,%9}, {%0,%1,%2,%3};\n"
        : "+f"(c[0]), "+f"(c[1]), "+f"(c[2]), "+f"(c[3])
        : "r"(__float_as_uint(a[0])), "r"(__float_as_uint(a[1])),
          "r"(__float_as_uint(a[2])), "r"(__float_as_uint(a[3])),
          "r"(__float_as_uint(b[0])), "r"(__float_as_uint(b[1])));
}
__device__ __forceinline__ void mma_f16(float* c, const uint32_t* a, const uint32_t* b) {
    asm volatile(
        "mma.sync.aligned.m16n8k16.row.col.f32.f16.f16.f32 "
        "{%0,%1,%2,%3}, {%4,%5,%6,%7}, {%8,%9}, {%0,%1,%2,%3};\n"
        : "+f"(c[0]), "+f"(c[1]), "+f"(c[2]), "+f"(c[3])
        : "r"(a[0]), "r"(a[1]), "r"(a[2]), "r"(a[3]),
          "r"(b[0]), "r"(b[1]));
}
__device__ __forceinline__ uint32_t pack_h2(float lo, float hi) {
    __half2 h = __floats2half2_rn(lo, hi);
    return *reinterpret_cast<uint32_t*>(&h);
}
__device__ __forceinline__ void cp_async16(uint32_t dst, const void* src) {
    asm volatile("cp.async.ca.shared.global [%0], [%1], 16;\n" :: "r"(dst), "l"(src));
}
#define CP_COMMIT() asm volatile("cp.async.commit_group;\n" ::: "memory")
#define CP_WAIT0()  asm volatile("cp.async.wait_group 0;\n" ::: "memory")

// ---------------- mask table build ----------------
__global__ void tab_kernel(const float* __restrict__ enc_W,
                           const float* __restrict__ enc_b,
                           const float* __restrict__ enc_g,
                           const float* __restrict__ enc_be,
                           float* __restrict__ tab)
{
    int w = (blockIdx.x * blockDim.x + threadIdx.x) >> 5;
    int lane = threadIdx.x & 31;
    const int NE = 3 * 2 * TABENT;
    if (w >= NE + 3) return;
    int i; float dir, mag;
    if (w < NE) {
        i = w / (2 * TABENT);
        int r = w - i * (2 * TABENT);
        int d = r / TABENT;
        int j = r - d * TABENT;
        dir = d ? 1.f : -1.f;
        float m0 = (float)j * (M0MAX / NTAB);
        float sc = (i == 0) ? 1.f : ((i == 1) ? 0.1f : 0.01f);
        mag = m0 * sc;
    } else {
        i = w - NE; dir = 0.f; mag = 0.f;
    }
    const float* W0 = enc_W + (size_t)(i*2+0)*DTS;
    const float* W1 = enc_W + (size_t)(i*2+1)*DTS;
    const float* bb = enc_b + (size_t)i*DTS;
    const float* gg = enc_g + (size_t)i*DTS;
    const float* be = enc_be + (size_t)i*DTS;

    float e[6];
    float s = 0.f, ss = 0.f;
    #pragma unroll
    for (int j2 = 0; j2 < 6; j2++) {
        int d = lane + 32*j2;
        float v = 0.f;
        if (d < DTS) v = dir*W0[d] + mag*W1[d] + bb[d];
        e[j2] = v; s += v; ss += v*v;
    }
    s  = warp_sum(s);
    ss = warp_sum(ss);
    float mean = s * (1.f/DTS);
    float var  = ss * (1.f/DTS) - mean*mean;
    float rs = rsqrtf(var + EPS);
    float gs = 0.f;
    #pragma unroll
    for (int j2 = 0; j2 < 6; j2++) {
        int d = lane + 32*j2;
        if (d < DTS) {
            float y = (e[j2] - mean) * rs * gg[d] + be[d];
            gs += gelu_exact(y);
        }
    }
    gs = warp_sum(gs);
    if (lane == 0) tab[w] = gs * (1.f/DTS);
}

// ---------------- mask fill via table interpolation ----------------
__global__ void maskfill_kernel(const float* __restrict__ ts,
                                const float* __restrict__ tab,
                                float* __restrict__ masks)
{
    int idx = blockIdx.x * blockDim.x + threadIdx.x;
    if (idx >= BSS) return;
    int b = idx >> 18;
    int q = (idx >> 9) & 511;
    int k = idx & 511;
    float dt = ts[(b << 9) + q] - ts[(b << 9) + k];
    if (dt == 0.f) {
        #pragma unroll
        for (int i = 0; i < TT; i++)
            masks[(size_t)i*BSS + idx] = tab[3*2*TABENT + i];
    } else {
        int d = dt > 0.f ? 1 : 0;
        float m0 = log1pf(fabsf(dt) * (1.f/3600.f));
        float t = m0 * ((float)NTAB / M0MAX);
        t = fminf(t, (float)NTAB - 1e-3f);
        int j = (int)t;
        float f = t - (float)j;
        #pragma unroll
        for (int i = 0; i < TT; i++) {
            const float* tb = tab + (size_t)(i*2 + d) * TABENT;
            float a = tb[j];
            masks[(size_t)i*BSS + idx] = a + f * (tb[j+1] - a);
        }
    }
}

// ---------------- fp16 tensor-core GEMM: BM=128, BK=16, m16n8k16 ----------------
// A layout: [row][12 words], word j holds half2 of k-pair j (j<4: pairs of first k8 group;
//           j in 4..7: pairs of upper k8 group). Fragment words c and c+4 -> banks 12g+c.
// B layout: [kpair][BNP words], word = half2 {B[2k][n], B[2k+1][n]}. Frag banks 8c+g.
template<int BN, int GELU>
__global__ __launch_bounds__(256)
void gemm_fp16(const float* __restrict__ A0, int lda,
               const float* __restrict__ B0, int ldb,
               const float* __restrict__ bias0,
               float* __restrict__ C0, int ldc, int K,
               size_t sAz, size_t sBz, size_t sCz, size_t sbz)
{
    constexpr int BM  = 128;
    constexpr int SAW = 12;                        // A row stride (words)
    constexpr int BNP = (BN == 128) ? 136 : 72;    // B kpair-row stride (words)
    constexpr int WN  = BN / 4;
    constexpr int NT2 = WN / 8;

    __shared__ __align__(16) uint32_t sA[2][BM*SAW];
    __shared__ __align__(16) uint32_t sB[2][8*BNP];

    const int tid  = threadIdx.x;
    const int lane = tid & 31;
    const int warp = tid >> 5;
    const int wm = warp & 1;
    const int wn = warp >> 1;
    const int g = lane >> 2;
    const int c = lane & 3;

    const int bm = blockIdx.y * BM;
    const int bn = blockIdx.x * BN;
    const int z  = blockIdx.z;

    const float* A = A0 + (size_t)z * sAz;
    const float* B = B0 + (size_t)z * sBz;
    const float* bias = bias0 + (size_t)z * sbz;
    float* C = C0 + (size_t)z * sCz;

    // A staging: thread -> row ar & ar+64, k-pairs ct and ct+4
    const int ar = tid >> 2;
    const int ct = tid & 3;
    const float* aP = A + (size_t)(bm + ar)*lda + 2*ct;   // float2 at +0 (pair ct) and +8 (pair ct+4)
    const float* aP2 = aP + (size_t)64*lda;

    // B staging
    const int bp = tid >> 5;                  // k-pair 0..7
    const int bnc = (BN == 128) ? (lane * 4) : (lane * 2);
    const float* bP0 = B + (size_t)(2*bp)*ldb + bn + bnc;
    const float* bP1 = bP0 + (size_t)ldb;

    float acc[4][NT2][4];
    #pragma unroll
    for (int i = 0; i < 4; i++)
        #pragma unroll
        for (int j = 0; j < NT2; j++)
            #pragma unroll
            for (int q = 0; q < 4; q++) acc[i][j][q] = 0.f;

    // staged register prefetch
    float2 a00, a01, a10, a11;          // rows ar / ar+64, pairs ct / ct+4
    float4 b0q, b1q;                    // BN=128 path
    float2 b0d, b1d;                    // BN=64 path

    auto loadG = [&](int k0) {
        a00 = *(const float2*)(aP + k0);
        a01 = *(const float2*)(aP + k0 + 8);
        a10 = *(const float2*)(aP2 + k0);
        a11 = *(const float2*)(aP2 + k0 + 8);
        if (BN == 128) {
            b0q = *(const float4*)(bP0 + (size_t)k0*ldb);
            b1q = *(const float4*)(bP1 + (size_t)k0*ldb);
        } else {
            b0d  = *(const float2*)(bP0 + (size_t)k0*ldb);
            b1d  = *(const float2*)(bP1 + (size_t)k0*ldb);
        }
    };
    auto storeS = [&](int buf) {
        sA[buf][ar*SAW + ct]          = pack_h2(a00.x, a00.y);
        sA[buf][ar*SAW + ct + 4]      = pack_h2(a01.x, a01.y);
        sA[buf][(ar+64)*SAW + ct]     = pack_h2(a10.x, a10.y);
        sA[buf][(ar+64)*SAW + ct + 4] = pack_h2(a11.x, a11.y);
        if (BN == 128) {
            uint4 w;
            w.x = pack_h2(b0q.x, b1q.x); w.y = pack_h2(b0q.y, b1q.y);
            w.z = pack_h2(b0q.z, b1q.z); w.w = pack_h2(b0q.w, b1q.w);
            *(uint4*)&sB[buf][bp*BNP + bnc] = w;
        } else {
            uint2 w;
            w.x = pack_h2(b0d.x, b1d.x); w.y = pack_h2(b0d.y, b1d.y);
            *(uint2*)&sB[buf][bp*BNP + bnc] = w;
        }
    };

    const int nstage = K / 16;
    loadG(0);
    storeS(0);
    __syncthreads();

    for (int s = 0; s < nstage; s++) {
        const int cur = s & 1;
        const bool more = (s + 1 < nstage);
        if (more) loadG((s + 1) * 16);

        uint32_t af[4][4];
        #pragma unroll
        for (int mt = 0; mt < 4; mt++) {
            const int rb = (wm*64 + mt*16 + g)*SAW;
            af[mt][0] = sA[cur][rb + c];
            af[mt][1] = sA[cur][rb + 8*SAW + c];
            af[mt][2] = sA[cur][rb + c + 4];
            af[mt][3] = sA[cur][rb + 8*SAW + c + 4];
        }
        uint32_t bf[NT2][2];
        #pragma unroll
        for (int nt = 0; nt < NT2; nt++) {
            const int n0 = wn*WN + nt*8 + g;
            bf[nt][0] = sB[cur][c*BNP + n0];
            bf[nt][1] = sB[cur][(c+4)*BNP + n0];
        }
        #pragma unroll
        for (int mt = 0; mt < 4; mt++)
            #pragma unroll
            for (int nt = 0; nt < NT2; nt++)
                mma_f16(acc[mt][nt], af[mt], bf[nt]);

        if (more) storeS(cur ^ 1);
        __syncthreads();
    }

    // epilogue (same accumulator mapping as tf32 m16n8)
    #pragma unroll
    for (int mt = 0; mt < 4; mt++) {
        const int row = bm + wm*64 + mt*16 + g;
        #pragma unroll
        for (int nt = 0; nt < NT2; nt++) {
            const int col = bn + wn*WN + nt*8 + c*2;
            float2 bb = *(const float2*)(bias + col);
            float v00 = acc[mt][nt][0] + bb.x, v01 = acc[mt][nt][1] + bb.y;
            float v10 = acc[mt][nt][2] + bb.x, v11 = acc[mt][nt][3] + bb.y;
            if (GELU) {
                v00 = gelu_exact(v00); v01 = gelu_exact(v01);
                v10 = gelu_exact(v10); v11 = gelu_exact(v11);
            }
            *(float2*)(C + (size_t)row*ldc + col) = make_float2(v00, v01);
            *(float2*)(C + (size_t)(row+8)*ldc + col) = make_float2(v10, v11);
        }
    }
}

// ---------------- fused flash attention (tf32, R6 proven) ----------------
#define QT 64
#define KT 64
#define FS 68
#define FTILE (64*FS)
#define FLASH_SMEM_BYTES (4*FTILE*4)

__global__ __launch_bounds__(128, 3)
void flash_kernel(const float* __restrict__ qkvb,
                  const float* __restrict__ maskb,
                  float* __restrict__ attnob)
{
    extern __shared__ float fsm[];

    const int qt = blockIdx.x;
    const int bh = blockIdx.y;
    const int t  = blockIdx.z;
    const int b = bh >> 3, h = bh & 7;
    const int tid = threadIdx.x;
    const int lane = tid & 31, warp = tid >> 5;
    const int g = lane >> 2, c = lane & 3;
    const int r0 = warp*16 + g, r1 = r0 + 8;

    const float* Qp = qkvb + (size_t)t*BS*1536 + (size_t)b*SS*1536 + h*DHH;
    const float* Kp = Qp + HH;
    const float* Vp = Qp + 2*HH;
    const float* Mp = maskb ? (maskb + (size_t)t*BSS + (size_t)b*SS*SS + (size_t)(qt*QT)*SS)
                            : nullptr;
    float* Op = attnob + (size_t)t*BS*HH + (size_t)b*SS*HH + h*DHH + (size_t)(qt*QT)*HH;

    const int srow = tid >> 1;
    const int shalf = (tid & 1) * 32;
    const uint32_t smemBase = (uint32_t)__cvta_generic_to_shared(fsm);
    const uint32_t rowOff = (uint32_t)((srow*FS + shalf) * 4);

    auto stageKV = [&](int tile, int buf) {
        const float* ksrc = Kp + (size_t)(tile*KT + srow)*1536 + shalf;
        const float* vsrc = Vp + (size_t)(tile*KT + srow)*1536 + shalf;
        uint32_t kdst = smemBase + (uint32_t)(buf*FTILE*4) + rowOff;
        uint32_t vdst = smemBase + (uint32_t)((2*FTILE + buf*FTILE)*4) + rowOff;
        #pragma unroll
        for (int j = 0; j < 8; j++) {
            cp_async16(kdst + j*16, ksrc + j*4);
            cp_async16(vdst + j*16, vsrc + j*4);
        }
    };

    {
        const float* qsrc = Qp + (size_t)(qt*QT + srow)*1536 + shalf;
        uint32_t qdst = smemBase + (uint32_t)(FTILE*4) + rowOff;
        #pragma unroll
        for (int j = 0; j < 8; j++) cp_async16(qdst + j*16, qsrc + j*4);
        stageKV(0, 0);
        CP_COMMIT();
        CP_WAIT0();
        __syncthreads();
    }

    float qf[8][4];
    {
        const float* sQ = fsm + FTILE;
        #pragma unroll
        for (int ks = 0; ks < 8; ks++) {
            qf[ks][0] = to_tf32(sQ[r0*FS + ks*8 + c]);
            qf[ks][1] = to_tf32(sQ[r1*FS + ks*8 + c]);
            qf[ks][2] = to_tf32(sQ[r0*FS + ks*8 + c + 4]);
            qf[ks][3] = to_tf32(sQ[r1*FS + ks*8 + c + 4]);
        }
    }
    __syncthreads();

    float of[8][4];
    #pragma unroll
    for (int nt = 0; nt < 8; nt++)
        #pragma unroll
        for (int q = 0; q < 4; q++) of[nt][q] = 0.f;
    float mA = -1e30f, lA = 0.f, mB = -1e30f, lB = 0.f;

    for (int kt = 0; kt < 8; kt++) {
        const int cur = kt & 1;
        const bool more = (kt + 1 < 8);
        if (more) { stageKV(kt + 1, cur ^ 1); CP_COMMIT(); }

        const float* sK = fsm + cur*FTILE;
        const float* sV = fsm + 2*FTILE + cur*FTILE;

        float sc[8][4];
        #pragma unroll
        for (int nt = 0; nt < 8; nt++)
            sc[nt][0] = sc[nt][1] = sc[nt][2] = sc[nt][3] = 0.f;
        #pragma unroll
        for (int ks = 0; ks < 8; ks++) {
            #pragma unroll
            for (int nt = 0; nt < 8; nt++) {
                const float* kp = sK + (nt*8 + g)*FS + ks*8;
                float bf[2] = { to_tf32(kp[c]), to_tf32(kp[c + 4]) };
                mma_tf32(sc[nt], qf[ks], bf);
            }
        }
        if (Mp) {
            const float* m0p = Mp + (size_t)r0*SS + kt*KT + 2*c;
            const float* m1p = Mp + (size_t)r1*SS + kt*KT + 2*c;
            #pragma unroll
            for (int nt = 0; nt < 8; nt++) {
                float2 u = *(const float2*)(m0p + nt*8);
                float2 v = *(const float2*)(m1p + nt*8);
                sc[nt][0] = sc[nt][0]*0.125f + u.x;
                sc[nt][1] = sc[nt][1]*0.125f + u.y;
                sc[nt][2] = sc[nt][2]*0.125f + v.x;
                sc[nt][3] = sc[nt][3]*0.125f + v.y;
            }
        } else {
            #pragma unroll
            for (int nt = 0; nt < 8; nt++) {
                sc[nt][0] *= 0.125f; sc[nt][1] *= 0.125f;
                sc[nt][2] *= 0.125f; sc[nt][3] *= 0.125f;
            }
        }
        float aMax = -1e30f, bMax = -1e30f;
        #pragma unroll
        for (int nt = 0; nt < 8; nt++) {
            aMax = fmaxf(aMax, fmaxf(sc[nt][0], sc[nt][1]));
            bMax = fmaxf(bMax, fmaxf(sc[nt][2], sc[nt][3]));
        }
        aMax = fmaxf(aMax, __shfl_xor_sync(0xffffffffu, aMax, 1));
        aMax = fmaxf(aMax, __shfl_xor_sync(0xffffffffu, aMax, 2));
        bMax = fmaxf(bMax, __shfl_xor_sync(0xffffffffu, bMax, 1));
        bMax = fmaxf(bMax, __shfl_xor_sync(0xffffffffu, bMax, 2));
        float mnA = fmaxf(mA, aMax), mnB = fmaxf(mB, bMax);
        float alA = __expf(mA - mnA), alB = __expf(mB - mnB);
        mA = mnA; mB = mnB;
        float sumA = 0.f, sumB = 0.f;
        #pragma unroll
        for (int nt = 0; nt < 8; nt++) {
            sc[nt][0] = __expf(sc[nt][0] - mnA); sumA += sc[nt][0];
            sc[nt][1] = __expf(sc[nt][1] - mnA); sumA += sc[nt][1];
            sc[nt][2] = __expf(sc[nt][2] - mnB); sumB += sc[nt][2];
            sc[nt][3] = __expf(sc[nt][3] - mnB); sumB += sc[nt][3];
        }
        sumA += __shfl_xor_sync(0xffffffffu, sumA, 1);
        sumA += __shfl_xor_sync(0xffffffffu, sumA, 2);
        sumB += __shfl_xor_sync(0xffffffffu, sumB, 1);
        sumB += __shfl_xor_sync(0xffffffffu, sumB, 2);
        lA = lA*alA + sumA;
        lB = lB*alB + sumB;
        #pragma unroll
        for (int nt = 0; nt < 8; nt++) {
            of[nt][0] *= alA; of[nt][1] *= alA;
            of[nt][2] *= alB; of[nt][3] *= alB;
        }

        #pragma unroll
        for (int ks = 0; ks < 8; ks++) {
            float af[4] = { to_tf32(sc[ks][0]), to_tf32(sc[ks][2]),
                            to_tf32(sc[ks][1]), to_tf32(sc[ks][3]) };
            #pragma unroll
            for (int nt = 0; nt < 8; nt++) {
                const float* vp = sV + (ks*8 + 2*c)*FS + nt*8 + g;
                float bf[2] = { to_tf32(vp[0]), to_tf32(vp[FS]) };
                mma_tf32(of[nt], af, bf);
            }
        }

        if (more) { CP_WAIT0(); }
        __syncthreads();
    }

    const float invA = 1.f / lA, invB = 1.f / lB;
    #pragma unroll
    for (int nt = 0; nt < 8; nt++) {
        const int col = nt*8 + 2*c;
        *(float2*)(Op + (size_t)r0*HH + col) =
            make_float2(of[nt][0]*invA, of[nt][1]*invA);
        *(float2*)(Op + (size_t)r1*HH + col) =
            make_float2(of[nt][2]*invB, of[nt][3]*invB);
    }
}

// ---------------- LayerNorm over 512 (+optional residual, +optional gelu) ----------------
__global__ void ln_kernel(const float* __restrict__ in, const float* __restrict__ res,
                          const float* __restrict__ g, const float* __restrict__ be,
                          float* __restrict__ out, int do_gelu)
{
    __shared__ float red[4];
    int row = blockIdx.x, tid = threadIdx.x;
    const float* ip = in + (size_t)row*HH;
    const float* rp = res ? (res + (size_t)row*HH) : nullptr;
    float v[4]; float s = 0.f;
    #pragma unroll
    for (int j = 0; j < 4; j++) {
        float x = ip[tid + 128*j];
        if (rp) x += rp[tid + 128*j];
        v[j] = x; s += x;
    }
    s = warp_sum(s);
    if ((tid & 31) == 0) red[tid >> 5] = s;
    __syncthreads();
    float mean = (red[0]+red[1]+red[2]+red[3]) * (1.f/HH);
    __syncthreads();
    float ss = 0.f;
    #pragma unroll
    for (int j = 0; j < 4; j++) { float d = v[j] - mean; ss += d*d; }
    ss = warp_sum(ss);
    if ((tid & 31) == 0) red[tid >> 5] = ss;
    __syncthreads();
    float var = (red[0]+red[1]+red[2]+red[3]) * (1.f/HH);
    float rs = rsqrtf(var + EPS);
    float* op = out + (size_t)row*HH;
    #pragma unroll
    for (int j = 0; j < 4; j++) {
        int cc = tid + 128*j;
        float y = (v[j] - mean) * rs * g[cc] + be[cc];
        if (do_gelu) y = gelu_exact(y);
        op[cc] = y;
    }
}

// ---------------- mixer: logits(3) -> softmax -> weighted combine ----------------
__global__ void mix_kernel(const float* __restrict__ mact, const float* __restrict__ W2,
                           const float* __restrict__ b2, const float* __restrict__ comb,
                           float* __restrict__ weighted)
{
    __shared__ float sl[3][4];
    __shared__ float smix[3];
    int row = blockIdx.x, tid = threadIdx.x;
    const float* mrow = mact + (size_t)row*HH;
    float l0 = 0.f, l1 = 0.f, l2 = 0.f;
    for (int d = tid; d < HH; d += 128) {
        float m = mrow[d];
        l0 += m * W2[d*3+0];
        l1 += m * W2[d*3+1];
        l2 += m * W2[d*3+2];
    }
    l0 = warp_sum(l0); l1 = warp_sum(l1); l2 = warp_sum(l2);
    int w = tid >> 5;
    if ((tid & 31) == 0) { sl[0][w] = l0; sl[1][w] = l1; sl[2][w] = l2; }
    __syncthreads();
    if (tid == 0) {
        float a0 = sl[0][0]+sl[0][1]+sl[0][2]+sl[0][3] + b2[0];
        float a1 = sl[1][0]+sl[1][1]+sl[1][2]+sl[1][3] + b2[1];
        float a2 = sl[2][0]+sl[2][1]+sl[2][2]+sl[2][3] + b2[2];
        float mx = fmaxf(a0, fmaxf(a1, a2));
        float e0 = expf(a0-mx), e1 = expf(a1-mx), e2 = expf(a2-mx);
        float inv = 1.f / (e0+e1+e2);
        smix[0] = e0*inv; smix[1] = e1*inv; smix[2] = e2*inv;
    }
    __syncthreads();
    float m0 = smix[0], m1 = smix[1], m2 = smix[2];
    const float* crow = comb + (size_t)row*(3*HH);
    float* wrow = weighted + (size_t)row*HH;
    for (int cc = tid; cc < HH; cc += 128)
        wrow[cc] = m0*crow[cc] + m1*crow[HH + cc] + m2*crow[2*HH + cc];
}

// ---------------- launch ----------------
extern "C" void kernel_launch(void* const* d_in, const int* in_sizes, int n_in,
                              void* d_out, int out_size)
{
    const float* x          = (const float*)d_in[0];
    const float* ts         = (const float*)d_in[1];
    const float* enc_W      = (const float*)d_in[2];
    const float* enc_b      = (const float*)d_in[3];
    const float* enc_ln_g   = (const float*)d_in[4];
    const float* enc_ln_b   = (const float*)d_in[5];
    const float* qkv_W      = (const float*)d_in[6];
    const float* qkv_b      = (const float*)d_in[7];
    const float* attn_out_W = (const float*)d_in[8];
    const float* attn_out_b = (const float*)d_in[9];
    const float* mixer_W1   = (const float*)d_in[10];
    const float* mixer_b1   = (const float*)d_in[11];
    const float* mixer_ln_g = (const float*)d_in[12];
    const float* mixer_ln_b = (const float*)d_in[13];
    const float* mixer_W2   = (const float*)d_in[14];
    const float* mixer_b2   = (const float*)d_in[15];
    const float* el_qkv_W   = (const float*)d_in[16];
    const float* el_qkv_b   = (const float*)d_in[17];
    const float* el_out_W   = (const float*)d_in[18];
    const float* el_out_b   = (const float*)d_in[19];
    const float* el_ln1_g   = (const float*)d_in[20];
    const float* el_ln1_b   = (const float*)d_in[21];
    const float* el_ff_W1   = (const float*)d_in[22];
    const float* el_ff_b1   = (const float*)d_in[23];
    const float* el_ff_W2   = (const float*)d_in[24];
    const float* el_ff_b2   = (const float*)d_in[25];
    const float* el_ln2_g   = (const float*)d_in[26];
    const float* el_ln2_b   = (const float*)d_in[27];
    const float* op_W       = (const float*)d_in[28];
    const float* op_b       = (const float*)d_in[29];
    const float* op_ln_g    = (const float*)d_in[30];
    const float* op_ln_b    = (const float*)d_in[31];
    float* out = (float*)d_out;

    float* base = nullptr;
    cudaGetSymbolAddress((void**)&base, g_scratch);
    float* maskv    = base + OFF_MASK;
    float* qkv      = base + OFF_QKV;
    float* attno    = base + OFF_ATTNO;
    float* comb     = base + OFF_COMB;
    float* mact     = base + OFF_MACT;
    float* weighted = base + OFF_WEIGHTED;
    float* sa       = base + OFF_SA;
    float* h1       = base + OFF_H1;
    float* ff       = base + OFF_FF;
    float* ffo      = base + OFF_FFO;
    float* h2       = base + OFF_H2;
    float* opb      = base + OFF_OP;
    float* tab      = base + OFF_TAB;

    cudaFuncSetAttribute(flash_kernel, cudaFuncAttributeMaxDynamicSharedMemorySize, FLASH_SMEM_BYTES);

    // 1. mask tables + fill
    {
        int nwarp = 3*2*TABENT + 3;
        int nblk = (nwarp*32 + 255) / 256;
        tab_kernel<<<nblk, 256>>>(enc_W, enc_b, enc_ln_g, enc_ln_b, tab);
        maskfill_kernel<<<(BSS + 255)/256, 256>>>(ts, tab, maskv);
    }

    // 2. per-timescale QKV (batched over z=3) + fused attention
    gemm_fp16<128,0><<<dim3(12,16,3), 256>>>(x, HH, qkv_W, 1536, qkv_b, qkv, 1536, HH,
                                             (size_t)0, (size_t)HH*1536, (size_t)BS*1536, (size_t)1536);
    flash_kernel<<<dim3(8, BB*NHH, 3), 128, FLASH_SMEM_BYTES>>>(qkv, maskv, attno);
    gemm_fp16<64,0><<<dim3(8,16,3), 256>>>(attno, HH, attn_out_W, HH, attn_out_b,
                                           comb, 1536, HH,
                                           (size_t)BS*HH, (size_t)HH*HH, (size_t)HH, (size_t)HH);

    // 3. time mixer
    gemm_fp16<64,0><<<dim3(8,16,1), 256>>>(comb, 1536, mixer_W1, HH, mixer_b1, mact, HH, 1536,
                                           (size_t)0,(size_t)0,(size_t)0,(size_t)0);
    ln_kernel<<<BS, 128>>>(mact, nullptr, mixer_ln_g, mixer_ln_b, mact, 1);
    mix_kernel<<<BS, 128>>>(mact, mixer_W2, mixer_b2, comb, weighted);

    // 4. transformer encoder layer (post-norm)
    gemm_fp16<128,0><<<dim3(12,16,1), 256>>>(weighted, HH, el_qkv_W, 1536, el_qkv_b, qkv, 1536, HH,
                                             (size_t)0,(size_t)0,(size_t)0,(size_t)0);
    flash_kernel<<<dim3(8, BB*NHH, 1), 128, FLASH_SMEM_BYTES>>>(qkv, nullptr, attno);
    gemm_fp16<64,0><<<dim3(8,16,1), 256>>>(attno, HH, el_out_W, HH, el_out_b, sa, HH, HH,
                                           (size_t)0,(size_t)0,(size_t)0,(size_t)0);
    ln_kernel<<<BS, 128>>>(sa, weighted, el_ln1_g, el_ln1_b, h1, 0);
    gemm_fp16<128,1><<<dim3(16,16,1), 256>>>(h1, HH, el_ff_W1, 2048, el_ff_b1, ff, 2048, HH,
                                             (size_t)0,(size_t)0,(size_t)0,(size_t)0);
    gemm_fp16<64,0><<<dim3(8,16,1), 256>>>(ff, 2048, el_ff_W2, HH, el_ff_b2, ffo, HH, 2048,
                                           (size_t)0,(size_t)0,(size_t)0,(size_t)0);
    ln_kernel<<<BS, 128>>>(ffo, h1, el_ln2_g, el_ln2_b, h2, 0);

    // 5. output projection + LN
    gemm_fp16<64,0><<<dim3(8,16,1), 256>>>(h2, HH, op_W, HH, op_b, opb, HH, HH,
                                           (size_t)0,(size_t)0,(size_t)0,(size_t)0);
    ln_kernel<<<BS, 128>>>(opb, nullptr, op_ln_g, op_ln_b, out, 0);
}